// round 8
// baseline (speedup 1.0000x reference)
#include <cuda_runtime.h>

#define NNODES 50000
#define NEDGES 800000
#define SCAN_T 1024

typedef unsigned long long u64;

__device__ __forceinline__ u64 fma2(u64 a, u64 b, u64 c) {
    u64 d;
    asm("fma.rn.f32x2 %0, %1, %2, %3;" : "=l"(d) : "l"(a), "l"(b), "l"(c));
    return d;
}

union F4U2 {
    float4 f4;
    ulonglong2 u2;
};

// ---- device-global scratch (allocation-free) ----
__device__ __align__(16) int   g_deg[NNODES];
__device__ __align__(16) int   g_rowptr[NNODES + 1];
__device__ __align__(16) int   g_cursor[NNODES];
__device__ __align__(16) int   g_csr_src[NEDGES];
__device__ __align__(16) float g_inv[NNODES];        // 1/max(deg,1)
__device__ __align__(16) float g_z[NNODES * 256];    // [z_l | z_r] stacked
__device__ __align__(16) float g_h1[NNODES * 128];
__device__ __align__(16) float g_h2[NNODES * 64];

// SEL: 0 = kernel parameter, 1 = g_h1, 2 = g_h2 (resolved in device code)
template <int SEL>
__device__ __forceinline__ const float* select_src(const float* p) {
    if (SEL == 1) return g_h1;
    if (SEL == 2) return g_h2;
    return p;
}
template <int SEL>
__device__ __forceinline__ float* select_dst(float* p) {
    if (SEL == 1) return g_h1;
    if (SEL == 2) return g_h2;
    return p;
}

// ---- CSR build (once; edge_index constant across layers) ----
__global__ void zero_deg_kernel() {
    int i = blockIdx.x * blockDim.x + threadIdx.x;
    if (i < NNODES) g_deg[i] = 0;
}

__global__ void count_kernel(const int* __restrict__ ei) {
    int e = blockIdx.x * blockDim.x + threadIdx.x;
    if (e < NEDGES) atomicAdd(&g_deg[ei[NEDGES + e]], 1);
}

__global__ void scan_kernel() {
    __shared__ int partial[SCAN_T];
    const int t = threadIdx.x;
    const int CH = (NNODES + SCAN_T - 1) / SCAN_T;
    const int base = t * CH;

    int s = 0;
    for (int i = 0; i < CH; i++) {
        int idx = base + i;
        if (idx < NNODES) s += g_deg[idx];
    }
    partial[t] = s;
    __syncthreads();
    for (int off = 1; off < SCAN_T; off <<= 1) {
        int add = (t >= off) ? partial[t - off] : 0;
        __syncthreads();
        partial[t] += add;
        __syncthreads();
    }
    int run = (t == 0) ? 0 : partial[t - 1];
    for (int i = 0; i < CH; i++) {
        int idx = base + i;
        if (idx < NNODES) {
            g_rowptr[idx] = run;
            g_cursor[idx] = run;
            g_inv[idx] = 1.0f / fmaxf((float)g_deg[idx], 1.0f);
            run += g_deg[idx];
        }
    }
    if (t == SCAN_T - 1) g_rowptr[NNODES] = partial[SCAN_T - 1];
}

__global__ void fill_kernel(const int* __restrict__ ei) {
    int e = blockIdx.x * blockDim.x + threadIdx.x;
    if (e < NEDGES) {
        int dst = ei[NEDGES + e];
        int slot = atomicAdd(&g_cursor[dst], 1);
        g_csr_src[slot] = ei[e];
    }
}

// ---- FMA2 SGEMM: z[n][j] = x[n].W[j], W = [Wl;Wr] stacked (2O rows) ----
// Per block: BM=128 nodes x 128 outs, BK=16, 256 threads, 8x8 per thread.
// Same tiling/register footprint as the round-6 FFMA version; inner product
// uses packed f32x2 FMAs (acc[8][4] u64 = 64 regs). A duplicated in smem so
// LDS.128 yields (a,a) pairs; B pairs are native layout.
template <int I, int O, int SRCSEL>
__global__ __launch_bounds__(256, 2)
void gemm2_kernel(const float* __restrict__ xp,
                  const float* __restrict__ Wl,
                  const float* __restrict__ Wr) {
    constexpr int BK = 16;
    __shared__ __align__(16) float asd[BK][2 * 128 + 8];  // duplicated A
    __shared__ __align__(16) float bs[BK][128 + 8];
    const float* x = select_src<SRCSEL>(xp);

    const int t  = threadIdx.x;
    const int m0 = blockIdx.x * 128;
    const int n0 = blockIdx.y * 128;
    const int tm = t & 15;   // m sub-tile: rows tm*8..tm*8+7
    const int tn = t >> 4;   // n sub-tile: cols tn*8..tn*8+7

    __align__(16) u64 acc[8][4];
#pragma unroll
    for (int i = 0; i < 8; i++)
#pragma unroll
        for (int j = 0; j < 4; j++) acc[i][j] = 0ULL;

    for (int k0 = 0; k0 < I; k0 += BK) {
        // A tile: 128 rows x 16 k, duplicate-stored (512 float4 over 256 thr)
#pragma unroll
        for (int r = 0; r < 2; r++) {
            int f   = t + r * 256;
            int row = f >> 2;
            int kq  = (f & 3) * 4;
            int node = m0 + row;
            float4 av = make_float4(0.f, 0.f, 0.f, 0.f);
            if (node < NNODES)
                av = *reinterpret_cast<const float4*>(x + (size_t)node * I + k0 + kq);
            asd[kq + 0][2 * row] = av.x;  asd[kq + 0][2 * row + 1] = av.x;
            asd[kq + 1][2 * row] = av.y;  asd[kq + 1][2 * row + 1] = av.y;
            asd[kq + 2][2 * row] = av.z;  asd[kq + 2][2 * row + 1] = av.z;
            asd[kq + 3][2 * row] = av.w;  asd[kq + 3][2 * row + 1] = av.w;
        }
        // B tile: 128 rows x 16 k (512 float4 over 256 thr)
#pragma unroll
        for (int r = 0; r < 2; r++) {
            int f  = t + r * 256;
            int jr = f >> 2;             // 0..127 within tile
            int kq = (f & 3) * 4;
            int j  = n0 + jr;
            const float* wrow = (j < O) ? (Wl + (size_t)j * I)
                                        : (Wr + (size_t)(j - O) * I);
            float4 bv = *reinterpret_cast<const float4*>(wrow + k0 + kq);
            bs[kq + 0][jr] = bv.x;
            bs[kq + 1][jr] = bv.y;
            bs[kq + 2][jr] = bv.z;
            bs[kq + 3][jr] = bv.w;
        }
        __syncthreads();
#pragma unroll
        for (int k = 0; k < BK; k++) {
            F4U2 a0, a1, a2, a3, b0, b1;
            const float* ar = &asd[k][16 * tm];   // 8 m values, duplicated
            a0.f4 = *reinterpret_cast<const float4*>(ar + 0);
            a1.f4 = *reinterpret_cast<const float4*>(ar + 4);
            a2.f4 = *reinterpret_cast<const float4*>(ar + 8);
            a3.f4 = *reinterpret_cast<const float4*>(ar + 12);
            const float* br = &bs[k][8 * tn];     // 8 n values = 4 pairs
            b0.f4 = *reinterpret_cast<const float4*>(br + 0);
            b1.f4 = *reinterpret_cast<const float4*>(br + 4);
            u64 ad[8] = {a0.u2.x, a0.u2.y, a1.u2.x, a1.u2.y,
                         a2.u2.x, a2.u2.y, a3.u2.x, a3.u2.y};
            u64 bp[4] = {b0.u2.x, b0.u2.y, b1.u2.x, b1.u2.y};
#pragma unroll
            for (int mm = 0; mm < 8; mm++)
#pragma unroll
                for (int np = 0; np < 4; np++)
                    acc[mm][np] = fma2(ad[mm], bp[np], acc[mm][np]);
        }
        __syncthreads();
    }

    constexpr int RS = 2 * O;  // z row stride
#pragma unroll
    for (int mm = 0; mm < 8; mm++) {
        int node = m0 + tm * 8 + mm;
        if (node < NNODES) {
            float* zr = g_z + (size_t)node * RS + n0 + tn * 8;
            const float4* av = reinterpret_cast<const float4*>(&acc[mm][0]);
            *reinterpret_cast<float4*>(zr + 0) = av[0];
            *reinterpret_cast<float4*>(zr + 4) = av[1];
        }
    }
}

// ---- gather-add: h[n] = inv[n] * sum_{s in N(n)} z_l[s] + z_r[n] + b ----
template <int O, int DSTSEL>
__global__ void gather_add_kernel(const float* __restrict__ b,
                                  float* __restrict__ outp) {
    float* out = select_dst<DSTSEL>(outp);
    int warp = (blockIdx.x * blockDim.x + threadIdx.x) >> 5;
    int lane = threadIdx.x & 31;
    if (warp >= NNODES) return;
    int beg = g_rowptr[warp];
    int end = g_rowptr[warp + 1];
    float inv = g_inv[warp];
    constexpr int RS = 2 * O;

    if (O == 128) {
        float4 acc = make_float4(0.f, 0.f, 0.f, 0.f);
        int j = beg;
        for (; j + 3 < end; j += 4) {
            int s0 = g_csr_src[j], s1 = g_csr_src[j + 1];
            int s2 = g_csr_src[j + 2], s3 = g_csr_src[j + 3];
            float4 v0 = reinterpret_cast<const float4*>(g_z + (size_t)s0 * RS)[lane];
            float4 v1 = reinterpret_cast<const float4*>(g_z + (size_t)s1 * RS)[lane];
            float4 v2 = reinterpret_cast<const float4*>(g_z + (size_t)s2 * RS)[lane];
            float4 v3 = reinterpret_cast<const float4*>(g_z + (size_t)s3 * RS)[lane];
            acc.x += (v0.x + v1.x) + (v2.x + v3.x);
            acc.y += (v0.y + v1.y) + (v2.y + v3.y);
            acc.z += (v0.z + v1.z) + (v2.z + v3.z);
            acc.w += (v0.w + v1.w) + (v2.w + v3.w);
        }
        for (; j < end; j++) {
            int s0 = g_csr_src[j];
            float4 v0 = reinterpret_cast<const float4*>(g_z + (size_t)s0 * RS)[lane];
            acc.x += v0.x; acc.y += v0.y; acc.z += v0.z; acc.w += v0.w;
        }
        float4 zr = reinterpret_cast<const float4*>(g_z + (size_t)warp * RS + O)[lane];
        float4 bb = reinterpret_cast<const float4*>(b)[lane];
        float4 res;
        res.x = acc.x * inv + zr.x + bb.x;
        res.y = acc.y * inv + zr.y + bb.y;
        res.z = acc.z * inv + zr.z + bb.z;
        res.w = acc.w * inv + zr.w + bb.w;
        reinterpret_cast<float4*>(out + (size_t)warp * O)[lane] = res;
    } else {
        float2 acc = make_float2(0.f, 0.f);
        int j = beg;
        for (; j + 3 < end; j += 4) {
            int s0 = g_csr_src[j], s1 = g_csr_src[j + 1];
            int s2 = g_csr_src[j + 2], s3 = g_csr_src[j + 3];
            float2 v0 = reinterpret_cast<const float2*>(g_z + (size_t)s0 * RS)[lane];
            float2 v1 = reinterpret_cast<const float2*>(g_z + (size_t)s1 * RS)[lane];
            float2 v2 = reinterpret_cast<const float2*>(g_z + (size_t)s2 * RS)[lane];
            float2 v3 = reinterpret_cast<const float2*>(g_z + (size_t)s3 * RS)[lane];
            acc.x += (v0.x + v1.x) + (v2.x + v3.x);
            acc.y += (v0.y + v1.y) + (v2.y + v3.y);
        }
        for (; j < end; j++) {
            int s0 = g_csr_src[j];
            float2 v0 = reinterpret_cast<const float2*>(g_z + (size_t)s0 * RS)[lane];
            acc.x += v0.x; acc.y += v0.y;
        }
        float2 zr = reinterpret_cast<const float2*>(g_z + (size_t)warp * RS + O)[lane];
        float2 bb = reinterpret_cast<const float2*>(b)[lane];
        float2 res;
        res.x = acc.x * inv + zr.x + bb.x;
        res.y = acc.y * inv + zr.y + bb.y;
        reinterpret_cast<float2*>(out + (size_t)warp * O)[lane] = res;
    }
}

extern "C" void kernel_launch(void* const* d_in, const int* in_sizes, int n_in,
                              void* d_out, int out_size) {
    const float* x   = (const float*)d_in[0];
    const int*   ei  = (const int*)d_in[1];   // int32 (JAX x64 disabled)
    const float* Wl1 = (const float*)d_in[2];
    const float* b1  = (const float*)d_in[3];
    const float* Wr1 = (const float*)d_in[4];
    const float* Wl2 = (const float*)d_in[5];
    const float* b2  = (const float*)d_in[6];
    const float* Wr2 = (const float*)d_in[7];
    const float* Wl3 = (const float*)d_in[8];
    const float* b3  = (const float*)d_in[9];
    const float* Wr3 = (const float*)d_in[10];
    float* out = (float*)d_out;

    const int TB = 256;
    const int MT = (NNODES + 127) / 128;          // 391 M-tiles
    const int GW = (NNODES * 32 + TB - 1) / TB;   // gather: warp/node

    // CSR build
    zero_deg_kernel<<<(NNODES + TB - 1) / TB, TB>>>();
    count_kernel<<<(NEDGES + TB - 1) / TB, TB>>>(ei);
    scan_kernel<<<1, SCAN_T>>>();
    fill_kernel<<<(NEDGES + TB - 1) / TB, TB>>>(ei);

    // Layer 1: I=128, O=128 (2 N-tiles)
    gemm2_kernel<128, 128, 0><<<dim3(MT, 2), 256>>>(x, Wl1, Wr1);
    gather_add_kernel<128, 1><<<GW, TB>>>(b1, nullptr);

    // Layer 2: I=128, O=64 (1 N-tile)
    gemm2_kernel<128, 64, 1><<<dim3(MT, 1), 256>>>(nullptr, Wl2, Wr2);
    gather_add_kernel<64, 2><<<GW, TB>>>(b2, nullptr);

    // Layer 3: I=64, O=128 (2 N-tiles)
    gemm2_kernel<64, 128, 2><<<dim3(MT, 2), 256>>>(nullptr, Wl3, Wr3);
    gather_add_kernel<128, 0><<<GW, TB>>>(b3, out);
}

// round 9
// speedup vs baseline: 1.5756x; 1.5756x over previous
#include <cuda_runtime.h>

#define NNODES 50000
#define NEDGES 800000
#define SCAN_T 1024

// ---- device-global scratch (allocation-free) ----
__device__ __align__(16) int   g_deg[NNODES];
__device__ __align__(16) int   g_rowptr[NNODES + 1];
__device__ __align__(16) int   g_cursor[NNODES];
__device__ __align__(16) int   g_csr_src[NEDGES];
__device__ __align__(16) float g_inv[NNODES];        // 1/max(deg,1)
__device__ __align__(16) float g_z[NNODES * 256];    // [z_l | z_r] stacked
__device__ __align__(16) float g_h1[NNODES * 128];
__device__ __align__(16) float g_h2[NNODES * 64];

// SEL: 0 = kernel parameter, 1 = g_h1, 2 = g_h2 (resolved in device code)
template <int SEL>
__device__ __forceinline__ const float* select_src(const float* p) {
    if (SEL == 1) return g_h1;
    if (SEL == 2) return g_h2;
    return p;
}
template <int SEL>
__device__ __forceinline__ float* select_dst(float* p) {
    if (SEL == 1) return g_h1;
    if (SEL == 2) return g_h2;
    return p;
}

// ---- CSR build (once; edge_index constant across layers) ----
__global__ void zero_deg_kernel() {
    int i = blockIdx.x * blockDim.x + threadIdx.x;
    if (i < NNODES) g_deg[i] = 0;
}

__global__ void count_kernel(const int* __restrict__ ei) {
    int e = blockIdx.x * blockDim.x + threadIdx.x;
    if (e < NEDGES) atomicAdd(&g_deg[ei[NEDGES + e]], 1);
}

__global__ void scan_kernel() {
    __shared__ int partial[SCAN_T];
    const int t = threadIdx.x;
    const int CH = (NNODES + SCAN_T - 1) / SCAN_T;
    const int base = t * CH;

    int s = 0;
    for (int i = 0; i < CH; i++) {
        int idx = base + i;
        if (idx < NNODES) s += g_deg[idx];
    }
    partial[t] = s;
    __syncthreads();
    for (int off = 1; off < SCAN_T; off <<= 1) {
        int add = (t >= off) ? partial[t - off] : 0;
        __syncthreads();
        partial[t] += add;
        __syncthreads();
    }
    int run = (t == 0) ? 0 : partial[t - 1];
    for (int i = 0; i < CH; i++) {
        int idx = base + i;
        if (idx < NNODES) {
            g_rowptr[idx] = run;
            g_cursor[idx] = run;
            g_inv[idx] = 1.0f / fmaxf((float)g_deg[idx], 1.0f);
            run += g_deg[idx];
        }
    }
    if (t == SCAN_T - 1) g_rowptr[NNODES] = partial[SCAN_T - 1];
}

__global__ void fill_kernel(const int* __restrict__ ei) {
    int e = blockIdx.x * blockDim.x + threadIdx.x;
    if (e < NEDGES) {
        int dst = ei[NEDGES + e];
        int slot = atomicAdd(&g_cursor[dst], 1);
        g_csr_src[slot] = ei[e];
    }
}

// ---- FFMA SGEMM, register-double-buffered ----
// z[n][j] = x[n] . W[j], W = [Wl;Wr] stacked (2O rows).
// BM=128, BN=128 (grid.y tiles), BK=16, 256 threads, 8x8 per thread.
// Iter i: LDG tile i+1 -> regs; compute smem[buf i]; STS regs -> smem[buf i^1];
// ONE __syncthreads per iter (vs 2 in the unpipelined version).
template <int I, int O, int SRCSEL>
__global__ __launch_bounds__(256, 2)
void gemm_kernel(const float* __restrict__ xp,
                 const float* __restrict__ Wl,
                 const float* __restrict__ Wr) {
    constexpr int BK = 16;
    __shared__ float as[2][BK][132];  // [buf][k][node], padded
    __shared__ float bs[2][BK][132];  // [buf][k][out]
    const float* x = select_src<SRCSEL>(xp);

    const int t  = threadIdx.x;
    const int m0 = blockIdx.x * 128;
    const int n0 = blockIdx.y * 128;
    const int mi = (t & 15) * 8;
    const int ni = (t >> 4) * 8;

    // Per-thread tile-load coordinates (fixed across iters): 512 float4 / 256 thr
    const int f0   = t;            // r=0
    const int f1   = t + 256;      // r=1
    const int row0 = f0 >> 2, kq0 = (f0 & 3) * 4;
    const int row1 = f1 >> 2, kq1 = (f1 & 3) * 4;

    float4 aR0, aR1, bR0, bR1;

    auto ldg_tile = [&](int k0) {
        int node0 = m0 + row0;
        aR0 = (node0 < NNODES)
                ? *reinterpret_cast<const float4*>(x + (size_t)node0 * I + k0 + kq0)
                : make_float4(0.f, 0.f, 0.f, 0.f);
        int node1 = m0 + row1;
        aR1 = (node1 < NNODES)
                ? *reinterpret_cast<const float4*>(x + (size_t)node1 * I + k0 + kq1)
                : make_float4(0.f, 0.f, 0.f, 0.f);
        int j0 = n0 + row0;
        const float* w0 = (j0 < O) ? (Wl + (size_t)j0 * I) : (Wr + (size_t)(j0 - O) * I);
        bR0 = *reinterpret_cast<const float4*>(w0 + k0 + kq0);
        int j1 = n0 + row1;
        const float* w1 = (j1 < O) ? (Wl + (size_t)j1 * I) : (Wr + (size_t)(j1 - O) * I);
        bR1 = *reinterpret_cast<const float4*>(w1 + k0 + kq1);
    };
    auto sts_tile = [&](int buf) {
        as[buf][kq0 + 0][row0] = aR0.x;
        as[buf][kq0 + 1][row0] = aR0.y;
        as[buf][kq0 + 2][row0] = aR0.z;
        as[buf][kq0 + 3][row0] = aR0.w;
        as[buf][kq1 + 0][row1] = aR1.x;
        as[buf][kq1 + 1][row1] = aR1.y;
        as[buf][kq1 + 2][row1] = aR1.z;
        as[buf][kq1 + 3][row1] = aR1.w;
        bs[buf][kq0 + 0][row0] = bR0.x;
        bs[buf][kq0 + 1][row0] = bR0.y;
        bs[buf][kq0 + 2][row0] = bR0.z;
        bs[buf][kq0 + 3][row0] = bR0.w;
        bs[buf][kq1 + 0][row1] = bR1.x;
        bs[buf][kq1 + 1][row1] = bR1.y;
        bs[buf][kq1 + 2][row1] = bR1.z;
        bs[buf][kq1 + 3][row1] = bR1.w;
    };

    float acc[8][8];
#pragma unroll
    for (int i = 0; i < 8; i++)
#pragma unroll
        for (int j = 0; j < 8; j++) acc[i][j] = 0.0f;

    // Prologue: fill buffer 0
    ldg_tile(0);
    sts_tile(0);
    __syncthreads();

    constexpr int NIT = I / BK;
#pragma unroll
    for (int it = 0; it < NIT; it++) {
        const int buf = it & 1;
        if (it + 1 < NIT) ldg_tile((it + 1) * BK);  // LDGs hidden by compute below
#pragma unroll
        for (int k = 0; k < BK; k++) {
            float4 a0 = *reinterpret_cast<const float4*>(&as[buf][k][mi]);
            float4 a1 = *reinterpret_cast<const float4*>(&as[buf][k][mi + 4]);
            float4 b0 = *reinterpret_cast<const float4*>(&bs[buf][k][ni]);
            float4 b1 = *reinterpret_cast<const float4*>(&bs[buf][k][ni + 4]);
            float am[8] = {a0.x, a0.y, a0.z, a0.w, a1.x, a1.y, a1.z, a1.w};
            float bn[8] = {b0.x, b0.y, b0.z, b0.w, b1.x, b1.y, b1.z, b1.w};
#pragma unroll
            for (int mm = 0; mm < 8; mm++)
#pragma unroll
                for (int nn = 0; nn < 8; nn++)
                    acc[mm][nn] += am[mm] * bn[nn];
        }
        if (it + 1 < NIT) sts_tile(buf ^ 1);  // fills the buffer computed 2 iters ago
        __syncthreads();
    }

    constexpr int RS = 2 * O;  // z row stride
#pragma unroll
    for (int mm = 0; mm < 8; mm++) {
        int node = m0 + mi + mm;
        if (node < NNODES) {
            float* zr = g_z + (size_t)node * RS + n0 + ni;
            *reinterpret_cast<float4*>(zr + 0) =
                make_float4(acc[mm][0], acc[mm][1], acc[mm][2], acc[mm][3]);
            *reinterpret_cast<float4*>(zr + 4) =
                make_float4(acc[mm][4], acc[mm][5], acc[mm][6], acc[mm][7]);
        }
    }
}

// ---- gather-add: h[n] = inv[n] * sum_{s in N(n)} z_l[s] + z_r[n] + b ----
template <int O, int DSTSEL>
__global__ void gather_add_kernel(const float* __restrict__ b,
                                  float* __restrict__ outp) {
    float* out = select_dst<DSTSEL>(outp);
    int warp = (blockIdx.x * blockDim.x + threadIdx.x) >> 5;
    int lane = threadIdx.x & 31;
    if (warp >= NNODES) return;
    int beg = g_rowptr[warp];
    int end = g_rowptr[warp + 1];
    float inv = g_inv[warp];
    constexpr int RS = 2 * O;

    if (O == 128) {
        float4 acc = make_float4(0.f, 0.f, 0.f, 0.f);
        int j = beg;
        for (; j + 3 < end; j += 4) {
            int s0 = g_csr_src[j], s1 = g_csr_src[j + 1];
            int s2 = g_csr_src[j + 2], s3 = g_csr_src[j + 3];
            float4 v0 = reinterpret_cast<const float4*>(g_z + (size_t)s0 * RS)[lane];
            float4 v1 = reinterpret_cast<const float4*>(g_z + (size_t)s1 * RS)[lane];
            float4 v2 = reinterpret_cast<const float4*>(g_z + (size_t)s2 * RS)[lane];
            float4 v3 = reinterpret_cast<const float4*>(g_z + (size_t)s3 * RS)[lane];
            acc.x += (v0.x + v1.x) + (v2.x + v3.x);
            acc.y += (v0.y + v1.y) + (v2.y + v3.y);
            acc.z += (v0.z + v1.z) + (v2.z + v3.z);
            acc.w += (v0.w + v1.w) + (v2.w + v3.w);
        }
        for (; j < end; j++) {
            int s0 = g_csr_src[j];
            float4 v0 = reinterpret_cast<const float4*>(g_z + (size_t)s0 * RS)[lane];
            acc.x += v0.x; acc.y += v0.y; acc.z += v0.z; acc.w += v0.w;
        }
        float4 zr = reinterpret_cast<const float4*>(g_z + (size_t)warp * RS + O)[lane];
        float4 bb = reinterpret_cast<const float4*>(b)[lane];
        float4 res;
        res.x = acc.x * inv + zr.x + bb.x;
        res.y = acc.y * inv + zr.y + bb.y;
        res.z = acc.z * inv + zr.z + bb.z;
        res.w = acc.w * inv + zr.w + bb.w;
        reinterpret_cast<float4*>(out + (size_t)warp * O)[lane] = res;
    } else {
        float2 acc = make_float2(0.f, 0.f);
        int j = beg;
        for (; j + 3 < end; j += 4) {
            int s0 = g_csr_src[j], s1 = g_csr_src[j + 1];
            int s2 = g_csr_src[j + 2], s3 = g_csr_src[j + 3];
            float2 v0 = reinterpret_cast<const float2*>(g_z + (size_t)s0 * RS)[lane];
            float2 v1 = reinterpret_cast<const float2*>(g_z + (size_t)s1 * RS)[lane];
            float2 v2 = reinterpret_cast<const float2*>(g_z + (size_t)s2 * RS)[lane];
            float2 v3 = reinterpret_cast<const float2*>(g_z + (size_t)s3 * RS)[lane];
            acc.x += (v0.x + v1.x) + (v2.x + v3.x);
            acc.y += (v0.y + v1.y) + (v2.y + v3.y);
        }
        for (; j < end; j++) {
            int s0 = g_csr_src[j];
            float2 v0 = reinterpret_cast<const float2*>(g_z + (size_t)s0 * RS)[lane];
            acc.x += v0.x; acc.y += v0.y;
        }
        float2 zr = reinterpret_cast<const float2*>(g_z + (size_t)warp * RS + O)[lane];
        float2 bb = reinterpret_cast<const float2*>(b)[lane];
        float2 res;
        res.x = acc.x * inv + zr.x + bb.x;
        res.y = acc.y * inv + zr.y + bb.y;
        reinterpret_cast<float2*>(out + (size_t)warp * O)[lane] = res;
    }
}

extern "C" void kernel_launch(void* const* d_in, const int* in_sizes, int n_in,
                              void* d_out, int out_size) {
    const float* x   = (const float*)d_in[0];
    const int*   ei  = (const int*)d_in[1];   // int32 (JAX x64 disabled)
    const float* Wl1 = (const float*)d_in[2];
    const float* b1  = (const float*)d_in[3];
    const float* Wr1 = (const float*)d_in[4];
    const float* Wl2 = (const float*)d_in[5];
    const float* b2  = (const float*)d_in[6];
    const float* Wr2 = (const float*)d_in[7];
    const float* Wl3 = (const float*)d_in[8];
    const float* b3  = (const float*)d_in[9];
    const float* Wr3 = (const float*)d_in[10];
    float* out = (float*)d_out;

    const int TB = 256;
    const int MT = (NNODES + 127) / 128;          // 391 M-tiles
    const int GW = (NNODES * 32 + TB - 1) / TB;   // gather: warp/node

    // CSR build
    zero_deg_kernel<<<(NNODES + TB - 1) / TB, TB>>>();
    count_kernel<<<(NEDGES + TB - 1) / TB, TB>>>(ei);
    scan_kernel<<<1, SCAN_T>>>();
    fill_kernel<<<(NEDGES + TB - 1) / TB, TB>>>(ei);

    // Layer 1: I=128, O=128 (2 N-tiles)
    gemm_kernel<128, 128, 0><<<dim3(MT, 2), 256>>>(x, Wl1, Wr1);
    gather_add_kernel<128, 1><<<GW, TB>>>(b1, nullptr);

    // Layer 2: I=128, O=64 (1 N-tile)
    gemm_kernel<128, 64, 1><<<dim3(MT, 1), 256>>>(nullptr, Wl2, Wr2);
    gather_add_kernel<64, 2><<<GW, TB>>>(b2, nullptr);

    // Layer 3: I=64, O=128 (2 N-tiles)
    gemm_kernel<64, 128, 2><<<dim3(MT, 2), 256>>>(nullptr, Wl3, Wr3);
    gather_add_kernel<128, 0><<<GW, TB>>>(b3, out);
}